// round 2
// baseline (speedup 1.0000x reference)
#include <cuda_runtime.h>
#include <cuda_bf16.h>
#include <cstdint>

#define MAX_N 100000
#define FDIM  128

// Scratch (allocation-free: __device__ globals, referenced directly)
__device__ float g_H[(size_t)MAX_N * FDIM];
__device__ float g_A[(size_t)MAX_N * FDIM];
__device__ float g_O[(size_t)MAX_N * FDIM];
__device__ float g_deg[MAX_N];
__device__ float g_dinv[MAX_N];
__device__ float g_dinv2[MAX_N];

// ---------------------------------------------------------------------------
__global__ void k_zero_deg(int n) {
    int i = blockIdx.x * blockDim.x + threadIdx.x;
    if (i < n) g_deg[i] = 0.f;
}

__global__ void k_count_deg(const int* __restrict__ ei, int E) {
    int e = blockIdx.x * blockDim.x + threadIdx.x;
    if (e < E) {
        int d = ei[E + e];  // dst row
        atomicAdd(&g_deg[d], 1.0f);
    }
}

__global__ void k_dinv(int n) {
    int i = blockIdx.x * blockDim.x + threadIdx.x;
    if (i < n) {
        float di = rsqrtf(g_deg[i] + 1.0f);
        g_dinv[i]  = di;
        g_dinv2[i] = di * di;
    }
}

// ---------------------------------------------------------------------------
// GEMM: h = X @ W   (X: [N,128], W: [128,128])
// Also writes agg-init: agg = h * dinv2[row]  (self-loop contribution)
// Block: 256 threads, 64 rows. Thread t: row r0 = t/4, 32 cols at (t%4)*32.
__global__ __launch_bounds__(256) void k_gemm_agginit(
    const float* __restrict__ X, const float* __restrict__ W, int N)
{
    __shared__ float xs[64][33];
    __shared__ float ws[32][128];

    int t  = threadIdx.x;
    int r0 = t >> 2;
    int cg = (t & 3) * 32;
    int rowbase = blockIdx.x * 64;

    float acc[32];
#pragma unroll
    for (int j = 0; j < 32; j++) acc[j] = 0.f;

    for (int kc = 0; kc < 4; kc++) {
        // X tile: 64 rows x 32 k
#pragma unroll
        for (int i = 0; i < 8; i++) {
            int idx = t + i * 256;
            int rr = idx >> 5, kk = idx & 31;
            int grow = rowbase + rr;
            xs[rr][kk] = (grow < N) ? X[(size_t)grow * FDIM + kc * 32 + kk] : 0.f;
        }
        // W tile: 32 k x 128 cols
#pragma unroll
        for (int i = 0; i < 16; i++) {
            int idx = t + i * 256;
            int kk = idx >> 7, cc = idx & 127;
            ws[kk][cc] = W[(size_t)(kc * 32 + kk) * FDIM + cc];
        }
        __syncthreads();
#pragma unroll
        for (int k = 0; k < 32; k++) {
            float xv = xs[r0][k];
#pragma unroll
            for (int j = 0; j < 32; j++) acc[j] = fmaf(xv, ws[k][cg + j], acc[j]);
        }
        __syncthreads();
    }

    int grow = rowbase + r0;
    if (grow < N) {
        float d2 = g_dinv2[grow];
        float4* hp = (float4*)(g_H + (size_t)grow * FDIM + cg);
        float4* ap = (float4*)(g_A + (size_t)grow * FDIM + cg);
#pragma unroll
        for (int j = 0; j < 8; j++) {
            float4 v = make_float4(acc[4*j], acc[4*j+1], acc[4*j+2], acc[4*j+3]);
            hp[j] = v;
            float4 a = make_float4(v.x * d2, v.y * d2, v.z * d2, v.w * d2);
            ap[j] = a;
        }
    }
}

// ---------------------------------------------------------------------------
// Edge scatter: one warp per edge. agg[dst] += h[src] * dinv[src]*dinv[dst]
__global__ __launch_bounds__(256) void k_edge_scatter(
    const int* __restrict__ ei, int E)
{
    long long gt = (long long)blockIdx.x * blockDim.x + threadIdx.x;
    long long warp = gt >> 5;
    int lane = threadIdx.x & 31;
    if (warp >= E) return;

    int s = __ldg(&ei[warp]);
    int d = __ldg(&ei[E + warp]);
    float norm = __ldg(&g_dinv[s]) * __ldg(&g_dinv[d]);

    const float4* hv = (const float4*)(g_H + (size_t)s * FDIM);
    float4 v = __ldg(&hv[lane]);
    v.x *= norm; v.y *= norm; v.z *= norm; v.w *= norm;

    float* ap = g_A + (size_t)d * FDIM + lane * 4;
    asm volatile("red.global.add.v4.f32 [%0], {%1,%2,%3,%4};"
                 :: "l"(ap), "f"(v.x), "f"(v.y), "f"(v.z), "f"(v.w)
                 : "memory");
}

// ---------------------------------------------------------------------------
// Finalize: out = (agg + b)  with optional relu; float4 vectorized over N*128
__global__ void k_finalize(const float* __restrict__ b,
                           float* __restrict__ out, long long nvec, int relu)
{
    long long i = (long long)blockIdx.x * blockDim.x + threadIdx.x;
    if (i >= nvec) return;
    int colv = (int)(i & 31);  // 32 float4 groups per row of 128
    float4 a = ((const float4*)g_A)[i];
    const float4 bb = ((const float4*)b)[colv];
    a.x += bb.x; a.y += bb.y; a.z += bb.z; a.w += bb.w;
    if (relu) {
        a.x = fmaxf(a.x, 0.f); a.y = fmaxf(a.y, 0.f);
        a.z = fmaxf(a.z, 0.f); a.w = fmaxf(a.w, 0.f);
    }
    ((float4*)out)[i] = a;
}

// ---------------------------------------------------------------------------
extern "C" void kernel_launch(void* const* d_in, const int* in_sizes, int n_in,
                              void* d_out, int out_size)
{
    const float* x  = (const float*)d_in[0];
    const int*   ei = (const int*)d_in[1];   // int32! (JAX x64 disabled)
    const float* W1 = (const float*)d_in[2];
    const float* b1 = (const float*)d_in[3];
    const float* W2 = (const float*)d_in[4];
    const float* b2 = (const float*)d_in[5];
    const float* W3 = (const float*)d_in[6];
    const float* b3 = (const float*)d_in[7];
    float* out = (float*)d_out;

    int N = in_sizes[0] / FDIM;
    int E = in_sizes[1] / 2;

    float* O;
    cudaGetSymbolAddress((void**)&O, g_O);

    int nThr = 256;
    int nBlkN    = (N + nThr - 1) / nThr;
    int nBlkE    = (E + nThr - 1) / nThr;
    int nBlkGemm = (N + 63) / 64;
    long long edgeThreads = (long long)E * 32;
    int nBlkEdge = (int)((edgeThreads + nThr - 1) / nThr);
    long long nvec = (long long)N * FDIM / 4;
    int nBlkFin  = (int)((nvec + nThr - 1) / nThr);

    // degree + dinv (once; shared by all three layers)
    k_zero_deg<<<nBlkN, nThr>>>(N);
    k_count_deg<<<nBlkE, nThr>>>(ei, E);
    k_dinv<<<nBlkN, nThr>>>(N);

    // Layer 1: in = x, out = O (relu)
    k_gemm_agginit<<<nBlkGemm, nThr>>>(x, W1, N);
    k_edge_scatter<<<nBlkEdge, nThr>>>(ei, E);
    k_finalize<<<nBlkFin, nThr>>>(b1, O, nvec, 1);

    // Layer 2: in = O, out = O (relu)
    k_gemm_agginit<<<nBlkGemm, nThr>>>(O, W2, N);
    k_edge_scatter<<<nBlkEdge, nThr>>>(ei, E);
    k_finalize<<<nBlkFin, nThr>>>(b2, O, nvec, 1);

    // Layer 3: in = O, out = d_out (no relu)
    k_gemm_agginit<<<nBlkGemm, nThr>>>(O, W3, N);
    k_edge_scatter<<<nBlkEdge, nThr>>>(ei, E);
    k_finalize<<<nBlkFin, nThr>>>(b3, out, nvec, 0);
}

// round 3
// speedup vs baseline: 3.0204x; 3.0204x over previous
#include <cuda_runtime.h>
#include <cuda_bf16.h>
#include <cstdint>

#define MAX_N 100000
#define FDIM  128

// Scratch (allocation-free: __device__ globals)
__device__ float g_H[(size_t)MAX_N * FDIM];
__device__ float g_A[(size_t)MAX_N * FDIM];
__device__ float g_O[(size_t)MAX_N * FDIM];
__device__ float g_deg[MAX_N];
__device__ float g_dinv[MAX_N];
__device__ float g_dinv2[MAX_N];

// ---------------------------------------------------------------------------
__global__ void k_zero_deg(int n) {
    int i = blockIdx.x * blockDim.x + threadIdx.x;
    if (i < n) g_deg[i] = 0.f;
}

__global__ void k_count_deg(const int* __restrict__ ei, int E) {
    int e = blockIdx.x * blockDim.x + threadIdx.x;
    if (e < E) {
        int d = ei[E + e];  // dst row
        atomicAdd(&g_deg[d], 1.0f);
    }
}

__global__ void k_dinv(int n) {
    int i = blockIdx.x * blockDim.x + threadIdx.x;
    if (i < n) {
        float di = rsqrtf(g_deg[i] + 1.0f);
        g_dinv[i]  = di;
        g_dinv2[i] = di * di;
    }
}

// ---------------------------------------------------------------------------
// Register-blocked SGEMM: h = X @ W, agg = h * dinv2[row]
// Tile: 128 rows x 128 cols (all outputs), K chunks of 32.
// 256 threads = 16x16; each thread owns an 8x8 micro-tile.
// Per k: 4x LDS.128 -> 64 FMA  (16 FMA per LDS instead of 1).
__global__ __launch_bounds__(256) void k_gemm_agginit(
    const float* __restrict__ X, const float* __restrict__ W, int N)
{
    __shared__ float xs[32][132];   // k-major: xs[k][row], pad 4 floats
    __shared__ float ws[32][132];   // ws[k][col]

    int t  = threadIdx.x;
    int tx = t & 15;        // col group: cols tx*8 .. +8
    int ty = t >> 4;        // row group: rows ty*8 .. +8
    int rowbase = blockIdx.x * 128;

    float acc[8][8];
#pragma unroll
    for (int i = 0; i < 8; i++)
#pragma unroll
        for (int j = 0; j < 8; j++) acc[i][j] = 0.f;

    for (int kc = 0; kc < 128; kc += 32) {
        // Load X tile [128 rows x 32 k], transposed into xs[k][row].
        // 1024 float4 loads, 4 per thread.
#pragma unroll
        for (int i = 0; i < 4; i++) {
            int idx = t + i * 256;          // 0..1023
            int row = idx >> 3;             // 0..127
            int kk4 = (idx & 7) * 4;        // 0,4,...,28
            int grow = rowbase + row;
            float4 v = (grow < N)
                ? *(const float4*)&X[(size_t)grow * FDIM + kc + kk4]
                : make_float4(0.f, 0.f, 0.f, 0.f);
            xs[kk4 + 0][row] = v.x;
            xs[kk4 + 1][row] = v.y;
            xs[kk4 + 2][row] = v.z;
            xs[kk4 + 3][row] = v.w;
        }
        // Load W tile [32 k x 128 cols] directly (already k-major).
#pragma unroll
        for (int i = 0; i < 4; i++) {
            int idx = t + i * 256;
            int kk  = idx >> 5;             // 0..31
            int cc4 = (idx & 31) * 4;       // 0..124
            *(float4*)&ws[kk][cc4] =
                *(const float4*)&W[(size_t)(kc + kk) * FDIM + cc4];
        }
        __syncthreads();

#pragma unroll
        for (int k = 0; k < 32; k++) {
            float xv[8], wv[8];
            *(float4*)&xv[0] = *(float4*)&xs[k][ty * 8];
            *(float4*)&xv[4] = *(float4*)&xs[k][ty * 8 + 4];
            *(float4*)&wv[0] = *(float4*)&ws[k][tx * 8];
            *(float4*)&wv[4] = *(float4*)&ws[k][tx * 8 + 4];
#pragma unroll
            for (int i = 0; i < 8; i++)
#pragma unroll
                for (int j = 0; j < 8; j++)
                    acc[i][j] = fmaf(xv[i], wv[j], acc[i][j]);
        }
        __syncthreads();
    }

    // Write h and agg-init = h * dinv2[row]
#pragma unroll
    for (int i = 0; i < 8; i++) {
        int grow = rowbase + ty * 8 + i;
        if (grow < N) {
            float d2 = g_dinv2[grow];
            float* hp = g_H + (size_t)grow * FDIM + tx * 8;
            float* ap = g_A + (size_t)grow * FDIM + tx * 8;
            float4 v0 = make_float4(acc[i][0], acc[i][1], acc[i][2], acc[i][3]);
            float4 v1 = make_float4(acc[i][4], acc[i][5], acc[i][6], acc[i][7]);
            *(float4*)(hp)     = v0;
            *(float4*)(hp + 4) = v1;
            *(float4*)(ap)     = make_float4(v0.x*d2, v0.y*d2, v0.z*d2, v0.w*d2);
            *(float4*)(ap + 4) = make_float4(v1.x*d2, v1.y*d2, v1.z*d2, v1.w*d2);
        }
    }
}

// ---------------------------------------------------------------------------
// Edge scatter: one warp per edge. agg[dst] += h[src] * dinv[src]*dinv[dst]
__global__ __launch_bounds__(256) void k_edge_scatter(
    const int* __restrict__ ei, int E)
{
    long long gt = (long long)blockIdx.x * blockDim.x + threadIdx.x;
    long long warp = gt >> 5;
    int lane = threadIdx.x & 31;
    if (warp >= E) return;

    int s = __ldg(&ei[warp]);
    int d = __ldg(&ei[E + warp]);
    float norm = __ldg(&g_dinv[s]) * __ldg(&g_dinv[d]);

    const float4* hv = (const float4*)(g_H + (size_t)s * FDIM);
    float4 v = __ldg(&hv[lane]);
    v.x *= norm; v.y *= norm; v.z *= norm; v.w *= norm;

    float* ap = g_A + (size_t)d * FDIM + lane * 4;
    asm volatile("red.global.add.v4.f32 [%0], {%1,%2,%3,%4};"
                 :: "l"(ap), "f"(v.x), "f"(v.y), "f"(v.z), "f"(v.w)
                 : "memory");
}

// ---------------------------------------------------------------------------
// Finalize: out = (agg + b) with optional relu; float4 vectorized
__global__ void k_finalize(const float* __restrict__ b,
                           float* __restrict__ out, long long nvec, int relu)
{
    long long i = (long long)blockIdx.x * blockDim.x + threadIdx.x;
    if (i >= nvec) return;
    int colv = (int)(i & 31);
    float4 a = ((const float4*)g_A)[i];
    const float4 bb = ((const float4*)b)[colv];
    a.x += bb.x; a.y += bb.y; a.z += bb.z; a.w += bb.w;
    if (relu) {
        a.x = fmaxf(a.x, 0.f); a.y = fmaxf(a.y, 0.f);
        a.z = fmaxf(a.z, 0.f); a.w = fmaxf(a.w, 0.f);
    }
    ((float4*)out)[i] = a;
}

// ---------------------------------------------------------------------------
extern "C" void kernel_launch(void* const* d_in, const int* in_sizes, int n_in,
                              void* d_out, int out_size)
{
    const float* x  = (const float*)d_in[0];
    const int*   ei = (const int*)d_in[1];   // int32 (JAX x64 disabled)
    const float* W1 = (const float*)d_in[2];
    const float* b1 = (const float*)d_in[3];
    const float* W2 = (const float*)d_in[4];
    const float* b2 = (const float*)d_in[5];
    const float* W3 = (const float*)d_in[6];
    const float* b3 = (const float*)d_in[7];
    float* out = (float*)d_out;

    int N = in_sizes[0] / FDIM;
    int E = in_sizes[1] / 2;

    float* O;
    cudaGetSymbolAddress((void**)&O, g_O);

    int nThr = 256;
    int nBlkN    = (N + nThr - 1) / nThr;
    int nBlkE    = (E + nThr - 1) / nThr;
    int nBlkGemm = (N + 127) / 128;
    long long edgeThreads = (long long)E * 32;
    int nBlkEdge = (int)((edgeThreads + nThr - 1) / nThr);
    long long nvec = (long long)N * FDIM / 4;
    int nBlkFin  = (int)((nvec + nThr - 1) / nThr);

    // degree + dinv (once; shared by all three layers)
    k_zero_deg<<<nBlkN, nThr>>>(N);
    k_count_deg<<<nBlkE, nThr>>>(ei, E);
    k_dinv<<<nBlkN, nThr>>>(N);

    // Layer 1: in = x, out = O (relu)
    k_gemm_agginit<<<nBlkGemm, nThr>>>(x, W1, N);
    k_edge_scatter<<<nBlkEdge, nThr>>>(ei, E);
    k_finalize<<<nBlkFin, nThr>>>(b1, O, nvec, 1);

    // Layer 2: in = O, out = O (relu)
    k_gemm_agginit<<<nBlkGemm, nThr>>>(O, W2, N);
    k_edge_scatter<<<nBlkEdge, nThr>>>(ei, E);
    k_finalize<<<nBlkFin, nThr>>>(b2, O, nvec, 1);

    // Layer 3: in = O, out = d_out (no relu)
    k_gemm_agginit<<<nBlkGemm, nThr>>>(O, W3, N);
    k_edge_scatter<<<nBlkEdge, nThr>>>(ei, E);
    k_finalize<<<nBlkFin, nThr>>>(b3, out, nvec, 0);
}

// round 4
// speedup vs baseline: 5.7578x; 1.9063x over previous
#include <cuda_runtime.h>
#include <cuda_bf16.h>
#include <cstdint>

#define MAX_N 100000
#define MAX_E 1700000
#define FDIM  128
#define CHUNK 1024   // scan chunk (256 thr x 4)

// Scratch (allocation-free: __device__ globals)
__device__ float g_H[(size_t)MAX_N * FDIM];
__device__ float g_O[(size_t)MAX_N * FDIM];
__device__ float g_dinv[MAX_N];
__device__ float g_dinv2[MAX_N];
__device__ int   g_cnt[MAX_N];        // in-degree
__device__ int   g_pos[MAX_N];        // per-chunk exclusive scan
__device__ int   g_rowStart[MAX_N];   // CSR row offsets
__device__ int   g_wcur[MAX_N];       // scatter cursors
__device__ int   g_chunkSum[256];
__device__ int   g_es[MAX_E];         // CSR src index
__device__ float g_en[MAX_E];         // CSR edge norm

// ---------------------------------------------------------------------------
__global__ void k_zero_cnt(int n) {
    int i = blockIdx.x * blockDim.x + threadIdx.x;
    if (i < n) g_cnt[i] = 0;
}

__global__ void k_hist(const int* __restrict__ ei, int E) {
    int e = blockIdx.x * blockDim.x + threadIdx.x;
    if (e < E) atomicAdd(&g_cnt[ei[E + e]], 1);
}

// Per-chunk exclusive scan: 256 threads x 4 elements = 1024 per block.
__global__ __launch_bounds__(256) void k_scan1(int n) {
    __shared__ int sh[256];
    int t = threadIdx.x;
    int base = blockIdx.x * CHUNK + t * 4;
    int v0 = (base + 0 < n) ? g_cnt[base + 0] : 0;
    int v1 = (base + 1 < n) ? g_cnt[base + 1] : 0;
    int v2 = (base + 2 < n) ? g_cnt[base + 2] : 0;
    int v3 = (base + 3 < n) ? g_cnt[base + 3] : 0;
    int tsum = v0 + v1 + v2 + v3;
    sh[t] = tsum;
    __syncthreads();
    // Hillis-Steele inclusive scan
    for (int off = 1; off < 256; off <<= 1) {
        int x = (t >= off) ? sh[t - off] : 0;
        __syncthreads();
        sh[t] += x;
        __syncthreads();
    }
    int texcl = sh[t] - tsum;
    if (base + 0 < n) g_pos[base + 0] = texcl;
    if (base + 1 < n) g_pos[base + 1] = texcl + v0;
    if (base + 2 < n) g_pos[base + 2] = texcl + v0 + v1;
    if (base + 3 < n) g_pos[base + 3] = texcl + v0 + v1 + v2;
    if (t == 255) g_chunkSum[blockIdx.x] = sh[255];
}

// Scan the (<=256) chunk sums, single block.
__global__ __launch_bounds__(256) void k_scan2(int nChunks) {
    __shared__ int sh[256];
    int t = threadIdx.x;
    int v = (t < nChunks) ? g_chunkSum[t] : 0;
    sh[t] = v;
    __syncthreads();
    for (int off = 1; off < 256; off <<= 1) {
        int x = (t >= off) ? sh[t - off] : 0;
        __syncthreads();
        sh[t] += x;
        __syncthreads();
    }
    if (t < nChunks) g_chunkSum[t] = sh[t] - v;  // exclusive
}

// Finalize row offsets; init cursors; compute dinv from degree.
__global__ void k_scan3(int n) {
    int i = blockIdx.x * blockDim.x + threadIdx.x;
    if (i < n) {
        int rs = g_pos[i] + g_chunkSum[i / CHUNK];
        g_rowStart[i] = rs;
        g_wcur[i]     = rs;
        float di = rsqrtf((float)g_cnt[i] + 1.0f);
        g_dinv[i]  = di;
        g_dinv2[i] = di * di;
    }
}

// Scatter edges into CSR order (by dst), precompute per-edge norm.
__global__ void k_build(const int* __restrict__ ei, int E) {
    int e = blockIdx.x * blockDim.x + threadIdx.x;
    if (e < E) {
        int s = ei[e];
        int d = ei[E + e];
        int p = atomicAdd(&g_wcur[d], 1);
        g_es[p] = s;
        g_en[p] = g_dinv[s] * g_dinv[d];
    }
}

// ---------------------------------------------------------------------------
// Register-blocked SGEMM: h = X @ W. 128x128 tile, 8x8 micro-tiles.
__global__ __launch_bounds__(256) void k_gemm(
    const float* __restrict__ X, const float* __restrict__ W, int N)
{
    __shared__ float xs[32][132];
    __shared__ float ws[32][132];

    int t  = threadIdx.x;
    int tx = t & 15;
    int ty = t >> 4;
    int rowbase = blockIdx.x * 128;

    float acc[8][8];
#pragma unroll
    for (int i = 0; i < 8; i++)
#pragma unroll
        for (int j = 0; j < 8; j++) acc[i][j] = 0.f;

    for (int kc = 0; kc < 128; kc += 32) {
#pragma unroll
        for (int i = 0; i < 4; i++) {
            int idx = t + i * 256;
            int row = idx >> 3;
            int kk4 = (idx & 7) * 4;
            int grow = rowbase + row;
            float4 v = (grow < N)
                ? *(const float4*)&X[(size_t)grow * FDIM + kc + kk4]
                : make_float4(0.f, 0.f, 0.f, 0.f);
            xs[kk4 + 0][row] = v.x;
            xs[kk4 + 1][row] = v.y;
            xs[kk4 + 2][row] = v.z;
            xs[kk4 + 3][row] = v.w;
        }
#pragma unroll
        for (int i = 0; i < 4; i++) {
            int idx = t + i * 256;
            int kk  = idx >> 5;
            int cc4 = (idx & 31) * 4;
            *(float4*)&ws[kk][cc4] =
                *(const float4*)&W[(size_t)(kc + kk) * FDIM + cc4];
        }
        __syncthreads();

#pragma unroll
        for (int k = 0; k < 32; k++) {
            float xv[8], wv[8];
            *(float4*)&xv[0] = *(float4*)&xs[k][ty * 8];
            *(float4*)&xv[4] = *(float4*)&xs[k][ty * 8 + 4];
            *(float4*)&wv[0] = *(float4*)&ws[k][tx * 8];
            *(float4*)&wv[4] = *(float4*)&ws[k][tx * 8 + 4];
#pragma unroll
            for (int i = 0; i < 8; i++)
#pragma unroll
                for (int j = 0; j < 8; j++)
                    acc[i][j] = fmaf(xv[i], wv[j], acc[i][j]);
        }
        __syncthreads();
    }

#pragma unroll
    for (int i = 0; i < 8; i++) {
        int grow = rowbase + ty * 8 + i;
        if (grow < N) {
            float* hp = g_H + (size_t)grow * FDIM + tx * 8;
            *(float4*)(hp)     = make_float4(acc[i][0], acc[i][1], acc[i][2], acc[i][3]);
            *(float4*)(hp + 4) = make_float4(acc[i][4], acc[i][5], acc[i][6], acc[i][7]);
        }
    }
}

// ---------------------------------------------------------------------------
// Pull-based aggregation + bias + relu, fused.
// One warp per dst node; lane l owns floats [4l, 4l+4) of the feature row.
// out[row] = act( sum_e norm_e * h[src_e] + h[row]*dinv2[row] + b )
__global__ __launch_bounds__(256) void k_gather(
    const float* __restrict__ h, const float* __restrict__ b,
    float* __restrict__ out, int N, int relu)
{
    int warp = (blockIdx.x * 256 + threadIdx.x) >> 5;
    int lane = threadIdx.x & 31;
    if (warp >= N) return;

    int row   = warp;
    int start = g_rowStart[row];
    int cnt   = g_cnt[row];

    float d2 = g_dinv2[row];
    float4 acc = __ldg((const float4*)(h + (size_t)row * FDIM) + lane);
    acc.x *= d2; acc.y *= d2; acc.z *= d2; acc.w *= d2;

    for (int e0 = 0; e0 < cnt; e0 += 32) {
        int mye = e0 + lane;
        int s = 0; float nm = 0.f;
        if (mye < cnt) {
            s  = __ldg(&g_es[start + mye]);
            nm = __ldg(&g_en[start + mye]);
        }
        int m = min(32, cnt - e0);
#pragma unroll 4
        for (int j = 0; j < m; j++) {
            int   sj = __shfl_sync(0xffffffffu, s,  j);
            float nj = __shfl_sync(0xffffffffu, nm, j);
            float4 v = __ldg((const float4*)(h + (size_t)sj * FDIM) + lane);
            acc.x = fmaf(v.x, nj, acc.x);
            acc.y = fmaf(v.y, nj, acc.y);
            acc.z = fmaf(v.z, nj, acc.z);
            acc.w = fmaf(v.w, nj, acc.w);
        }
    }

    float4 bb = __ldg((const float4*)b + lane);
    acc.x += bb.x; acc.y += bb.y; acc.z += bb.z; acc.w += bb.w;
    if (relu) {
        acc.x = fmaxf(acc.x, 0.f); acc.y = fmaxf(acc.y, 0.f);
        acc.z = fmaxf(acc.z, 0.f); acc.w = fmaxf(acc.w, 0.f);
    }
    ((float4*)(out + (size_t)row * FDIM))[lane] = acc;
}

// ---------------------------------------------------------------------------
extern "C" void kernel_launch(void* const* d_in, const int* in_sizes, int n_in,
                              void* d_out, int out_size)
{
    const float* x  = (const float*)d_in[0];
    const int*   ei = (const int*)d_in[1];   // int32 (JAX x64 disabled)
    const float* W1 = (const float*)d_in[2];
    const float* b1 = (const float*)d_in[3];
    const float* W2 = (const float*)d_in[4];
    const float* b2 = (const float*)d_in[5];
    const float* W3 = (const float*)d_in[6];
    const float* b3 = (const float*)d_in[7];
    float* out = (float*)d_out;

    int N = in_sizes[0] / FDIM;
    int E = in_sizes[1] / 2;

    float *H, *O;
    cudaGetSymbolAddress((void**)&H, g_H);
    cudaGetSymbolAddress((void**)&O, g_O);

    int nThr = 256;
    int nBlkN    = (N + nThr - 1) / nThr;
    int nBlkE    = (E + nThr - 1) / nThr;
    int nBlkGemm = (N + 127) / 128;
    int nChunks  = (N + CHUNK - 1) / CHUNK;
    long long gthreads = (long long)N * 32;
    int nBlkGather = (int)((gthreads + nThr - 1) / nThr);

    // --- CSR build (once per launch) ---
    k_zero_cnt<<<nBlkN, nThr>>>(N);
    k_hist<<<nBlkE, nThr>>>(ei, E);
    k_scan1<<<nChunks, nThr>>>(N);
    k_scan2<<<1, nThr>>>(nChunks);
    k_scan3<<<nBlkN, nThr>>>(N);
    k_build<<<nBlkE, nThr>>>(ei, E);

    // Layer 1: x -> H -> O (relu)
    k_gemm<<<nBlkGemm, nThr>>>(x, W1, N);
    k_gather<<<nBlkGather, nThr>>>(H, b1, O, N, 1);

    // Layer 2: O -> H -> O (relu)
    k_gemm<<<nBlkGemm, nThr>>>(O, W2, N);
    k_gather<<<nBlkGather, nThr>>>(H, b2, O, N, 1);

    // Layer 3: O -> H -> out (no relu)
    k_gemm<<<nBlkGemm, nThr>>>(O, W3, N);
    k_gather<<<nBlkGather, nThr>>>(H, b3, out, N, 0);
}